// round 7
// baseline (speedup 1.0000x reference)
#include <cuda_runtime.h>
#include <cstdint>

// out_i = sign(x) * u_i / ||u||, u = W[0,1:4]; 0 when x == 0.
// Persistent 3-stage cp.async.bulk pipeline: keeps ~48KB of input reads in
// flight per SM (vs ~7KB MSHR-limited LDG), overlaps bulk stores via
// bulk_group slack. 2 CTAs/SM x 3 stages x 8KB tiles.

#define HWPIX   (512 * 512)
#define NBATCH  16
#define TILE    2048                  // elements per tile (8KB)
#define TILE_B  (TILE * 4)
#define NTILES  ((NBATCH * HWPIX) / TILE)   // 2048
#define STAGES  3
#define GRID    296
#define THREADS 256
#define SMEM_BYTES ((STAGES * TILE + STAGES * 3 * TILE) * 4)   // 96KB

__device__ __forceinline__ void mbar_wait(uint32_t mbar_a, uint32_t parity) {
    uint32_t done;
    asm volatile(
        "{\n\t.reg .pred p;\n\t"
        "mbarrier.try_wait.parity.acquire.cta.shared::cta.b64 p, [%1], %2;\n\t"
        "selp.b32 %0, 1, 0, p;\n\t}"
        : "=r"(done) : "r"(mbar_a), "r"(parity) : "memory");
    if (!done) {
        asm volatile(
            "{\n\t.reg .pred P1;\n\t"
            "WAIT_LOOP_%=:\n\t"
            "mbarrier.try_wait.parity.acquire.cta.shared::cta.b64 P1, [%0], %1, 0x989680;\n\t"
            "@P1 bra.uni WAIT_DONE_%=;\n\t"
            "bra.uni WAIT_LOOP_%=;\n\t"
            "WAIT_DONE_%=:\n\t}"
            :: "r"(mbar_a), "r"(parity) : "memory");
    }
}

__global__ __launch_bounds__(THREADS) void scene_normal_kernel(
    const float* __restrict__ depth,    // [16*512*512]
    const float* __restrict__ Wm,       // [8,8]
    float* __restrict__ out)            // [16,3,512,512]
{
    extern __shared__ float smem[];
    float* s_in  = smem;                       // [STAGES][TILE]
    float* s_out = smem + STAGES * TILE;       // [STAGES][3][TILE]
    __shared__ alignas(8) unsigned long long mbar[STAGES];

    const int tid = threadIdx.x;
    const int bid = blockIdx.x;

    uint32_t mbar_a[STAGES];
#pragma unroll
    for (int s = 0; s < STAGES; s++)
        mbar_a[s] = (uint32_t)__cvta_generic_to_shared(&mbar[s]);

    if (tid == 0) {
#pragma unroll
        for (int s = 0; s < STAGES; s++)
            asm volatile("mbarrier.init.shared.b64 [%0], 1;" :: "r"(mbar_a[s]) : "memory");
    }
    __syncthreads();

    // Number of tiles this CTA handles (strided by GRID)
    const int nt = (NTILES - bid + GRID - 1) / GRID;

    // Prologue: fill the pipeline
    if (tid == 0) {
#pragma unroll
        for (int j = 0; j < STAGES; j++) {
            if (j < nt) {
                const int t = bid + j * GRID;
                const uint32_t dst = (uint32_t)__cvta_generic_to_shared(s_in + j * TILE);
                asm volatile("mbarrier.arrive.expect_tx.shared.b64 _, [%0], %1;"
                             :: "r"(mbar_a[j]), "r"(TILE_B) : "memory");
                asm volatile(
                    "cp.async.bulk.shared::cluster.global.mbarrier::complete_tx::bytes "
                    "[%0], [%1], %2, [%3];"
                    :: "r"(dst), "l"(depth + (size_t)t * TILE), "r"(TILE_B), "r"(mbar_a[j])
                    : "memory");
            }
        }
    }

    // Constants (overlap with in-flight loads)
    const float u1 = Wm[1];
    const float u2 = Wm[2];
    const float u3 = Wm[3];
    const float r  = rsqrtf(u1 * u1 + u2 * u2 + u3 * u3);
    const float c1 = u1 * r, c2 = u2 * r, c3 = u3 * r;

    for (int j = 0; j < nt; j++) {
        const int stage = j % STAGES;
        const uint32_t parity = (uint32_t)((j / STAGES) & 1);
        const int t  = bid + j * GRID;
        const int n0 = t * TILE;
        const int b  = n0 >> 18;
        const int rem = n0 & (HWPIX - 1);

        // Ensure s_out[stage] drained (keep at most 2 store groups pending)
        if (tid == 0)
            asm volatile("cp.async.bulk.wait_group 2;" ::: "memory");
        __syncthreads();

        // Wait for input tile
        mbar_wait(mbar_a[stage], parity);

        // Compute tile: 512 float4s / 256 threads = 2 each
        const float4* in4 = reinterpret_cast<const float4*>(s_in + stage * TILE);
        float4* o0 = reinterpret_cast<float4*>(s_out + (stage * 3 + 0) * TILE);
        float4* o1 = reinterpret_cast<float4*>(s_out + (stage * 3 + 1) * TILE);
        float4* o2 = reinterpret_cast<float4*>(s_out + (stage * 3 + 2) * TILE);
#pragma unroll
        for (int i = 0; i < TILE / 4 / THREADS; i++) {
            const int idx = tid + i * THREADS;
            const float4 x = in4[idx];
            const float s0 = (x.x > 0.f) ? 1.f : ((x.x < 0.f) ? -1.f : 0.f);
            const float s1 = (x.y > 0.f) ? 1.f : ((x.y < 0.f) ? -1.f : 0.f);
            const float s2 = (x.z > 0.f) ? 1.f : ((x.z < 0.f) ? -1.f : 0.f);
            const float s3 = (x.w > 0.f) ? 1.f : ((x.w < 0.f) ? -1.f : 0.f);
            o0[idx] = make_float4(s0 * c1, s1 * c1, s2 * c1, s3 * c1);
            o1[idx] = make_float4(s0 * c2, s1 * c2, s2 * c2, s3 * c2);
            o2[idx] = make_float4(s0 * c3, s1 * c3, s2 * c3, s3 * c3);
        }
        __syncthreads();

        if (tid == 0) {
            asm volatile("fence.proxy.async.shared::cta;" ::: "memory");
            float* dst = out + (size_t)b * 3 * HWPIX + rem;
#pragma unroll
            for (int pln = 0; pln < 3; pln++) {
                const uint32_t so =
                    (uint32_t)__cvta_generic_to_shared(s_out + (stage * 3 + pln) * TILE);
                asm volatile(
                    "cp.async.bulk.global.shared::cta.bulk_group [%0], [%1], %2;"
                    :: "l"(dst + (size_t)pln * HWPIX), "r"(so), "r"(TILE_B)
                    : "memory");
            }
            asm volatile("cp.async.bulk.commit_group;" ::: "memory");

            // Refill this stage with the tile STAGES ahead
            const int jn = j + STAGES;
            if (jn < nt) {
                const int tn = bid + jn * GRID;
                const uint32_t dsts = (uint32_t)__cvta_generic_to_shared(s_in + stage * TILE);
                asm volatile("mbarrier.arrive.expect_tx.shared.b64 _, [%0], %1;"
                             :: "r"(mbar_a[stage]), "r"(TILE_B) : "memory");
                asm volatile(
                    "cp.async.bulk.shared::cluster.global.mbarrier::complete_tx::bytes "
                    "[%0], [%1], %2, [%3];"
                    :: "r"(dsts), "l"(depth + (size_t)tn * TILE), "r"(TILE_B), "r"(mbar_a[stage])
                    : "memory");
            }
        }
    }

    // Drain all pending stores before CTA exit
    if (tid == 0)
        asm volatile("cp.async.bulk.wait_group 0;" ::: "memory");
    __syncthreads();
}

extern "C" void kernel_launch(void* const* d_in, const int* in_sizes, int n_in,
                              void* d_out, int out_size)
{
    const float* depth = (const float*)d_in[0];
    const float* Wm    = (const float*)d_in[1];
    float* out         = (float*)d_out;

    cudaFuncSetAttribute(scene_normal_kernel,
                         cudaFuncAttributeMaxDynamicSharedMemorySize, SMEM_BYTES);

    scene_normal_kernel<<<GRID, THREADS, SMEM_BYTES>>>(depth, Wm, out);
}